// round 15
// baseline (speedup 1.0000x reference)
#include <cuda_runtime.h>
#include <cuda_bf16.h>
#include <cuda_fp16.h>
#include <cstdint>
#include <math.h>

#define S_LEN 16384
#define HID 1280
#define NH 16
#define HD 80
#define NC 16
#define CH 1024

// ---------------------------------------------------------------------------
// Scratch (no cudaMalloc allowed)
// ---------------------------------------------------------------------------
__device__ __align__(256) __half g_xf[(size_t)S_LEN * HID];
__device__ __align__(256) __half g_wq[(size_t)3 * HID * HID];  // q/k rows PERMUTED
__device__ __align__(256) float  g_bq[3 * HID];                // permuted bias
__device__ __align__(256) __half g_wp[(size_t)HID * HID];
// rope table: (cos_i, cos_{i+40}, sin_i, sin_{i+40}) per (t, pair i)
__device__ __align__(256) float4 g_rope[(size_t)S_LEN * 40];
// attention inputs: plain fp16, q/k in rope-permuted d-layout,
// q pre-scaled by 1/sqrt(80)*log2e
__device__ __align__(256) __half g_qf[(size_t)S_LEN * HID];
__device__ __align__(256) __half g_kf[(size_t)S_LEN * HID];
__device__ __align__(256) __half g_vf[(size_t)S_LEN * HID];
// attention output = proj GEMM activation (fp16)
__device__ __align__(256) __half g_af[(size_t)S_LEN * HID];

#define QSCALE 0.16130856f   // 0.11180339887 * 1.44269504089

// ---------------------------------------------------------------------------
// helpers (sm_80-era instructions only — harness compiles for plain sm_103)
// ---------------------------------------------------------------------------
__device__ __forceinline__ uint32_t smem_u32(const void* p) {
    uint32_t a;
    asm("{ .reg .u64 t; cvta.to.shared.u64 t, %1; cvt.u32.u64 %0, t; }"
        : "=r"(a) : "l"(p));
    return a;
}

__device__ __forceinline__ void cpa16(uint32_t dst, const void* src) {
    asm volatile("cp.async.cg.shared.global [%0], [%1], 16;\n"
                 :: "r"(dst), "l"(src));
}
__device__ __forceinline__ void cpa_commit() {
    asm volatile("cp.async.commit_group;\n" ::: "memory");
}
template <int N>
__device__ __forceinline__ void cpa_wait() {
    asm volatile("cp.async.wait_group %0;\n" :: "n"(N) : "memory");
}

__device__ __forceinline__ void ldm_x4(uint32_t* r, uint32_t addr) {
    asm volatile("ldmatrix.sync.aligned.m8n8.x4.shared.b16 {%0,%1,%2,%3}, [%4];"
                 : "=r"(r[0]), "=r"(r[1]), "=r"(r[2]), "=r"(r[3])
                 : "r"(addr));
}
__device__ __forceinline__ void ldm_x4_t(uint32_t* r, uint32_t addr) {
    asm volatile(
        "ldmatrix.sync.aligned.m8n8.x4.trans.shared.b16 {%0,%1,%2,%3}, [%4];"
        : "=r"(r[0]), "=r"(r[1]), "=r"(r[2]), "=r"(r[3])
        : "r"(addr));
}

__device__ __forceinline__ void mma16816h(float* d, const uint32_t* a,
                                          const uint32_t* b) {
    asm volatile(
        "mma.sync.aligned.m16n8k16.row.col.f32.f16.f16.f32 "
        "{%0,%1,%2,%3}, {%4,%5,%6,%7}, {%8,%9}, {%0,%1,%2,%3};"
        : "+f"(d[0]), "+f"(d[1]), "+f"(d[2]), "+f"(d[3])
        : "r"(a[0]), "r"(a[1]), "r"(a[2]), "r"(a[3]), "r"(b[0]), "r"(b[1]));
}

__device__ __forceinline__ uint32_t pack_f16(float lo, float hi) {
    uint32_t d;
    asm("cvt.rn.f16x2.f32 %0, %1, %2;" : "=r"(d) : "f"(hi), "f"(lo));
    return d;
}

// ---------------------------------------------------------------------------
// Fused prep: x cvt | wq perm cvt (+bias) | wp cvt | rope table
// ---------------------------------------------------------------------------
#define N_X   (S_LEN * HID)
#define N_WQ  (3 * HID * HID)
#define N_WP  (HID * HID)
#define SEG0  (N_X / 4)
#define SEG1  (SEG0 + N_WQ / 4)
#define SEG2  (SEG1 + N_WP / 4)
#define SEG3  (SEG2 + S_LEN * 40)

__global__ void prep_all(const float* __restrict__ x,
                         const float* __restrict__ w_qkv,
                         const float* __restrict__ b_qkv,
                         const float* __restrict__ w_proj,
                         const float* __restrict__ cosb,
                         const float* __restrict__ sinb)
{
    int u = blockIdx.x * blockDim.x + threadIdx.x;
    if (u < SEG0) {
        const int i = u * 4;
        float4 v = *(const float4*)(x + i);
        *(__half2*)(g_xf + i)     = __floats2half2_rn(v.x, v.y);
        *(__half2*)(g_xf + i + 2) = __floats2half2_rn(v.z, v.w);
    } else if (u < SEG1) {
        const int i = (u - SEG0) * 4;
        const int p  = i / HID;
        const int kk = i % HID;
        const int which = p / HID;
        int n = p;
        if (which < 2) {
            const int pl = p % HID;
            const int h = pl / 80, j = pl % 80;
            const int d = (j & 1) ? (j >> 1) + 40 : (j >> 1);
            n = which * HID + h * 80 + d;
        }
        float4 v = *(const float4*)(w_qkv + (size_t)n * HID + kk);
        *(__half2*)(g_wq + (size_t)p * HID + kk)     = __floats2half2_rn(v.x, v.y);
        *(__half2*)(g_wq + (size_t)p * HID + kk + 2) = __floats2half2_rn(v.z, v.w);
        if (kk == 0) g_bq[p] = b_qkv[n];
    } else if (u < SEG2) {
        const int i = (u - SEG1) * 4;
        float4 v = *(const float4*)(w_proj + i);
        *(__half2*)(g_wp + i)     = __floats2half2_rn(v.x, v.y);
        *(__half2*)(g_wp + i + 2) = __floats2half2_rn(v.z, v.w);
    } else if (u < SEG3) {
        const int e = u - SEG2;
        const int t = e / 40, i = e % 40;
        float4 r;
        r.x = cosb[t * HD + i];
        r.y = cosb[t * HD + i + 40];
        r.z = sinb[t * HD + i];
        r.w = sinb[t * HD + i + 40];
        g_rope[e] = r;
    }
}

// ---------------------------------------------------------------------------
// fp16 GEMM mainloop: block 128x128, K-chunk 64, 8 warps (4M x 2N),
// warp tile 32x64. 3-stage cp.async pipeline (wait<1> keeps one stage in
// flight), single __syncthreads per K-iter. smem 110592B -> still 2 CTAs/SM.
// Row stride 144B -> conflict-free ldmatrix (9*row mod 8 distinct).
// ---------------------------------------------------------------------------
#define GBM 128
#define GBN 128
#define GBK 64
#define ROWB 144
#define MAT_BYTES (128 * ROWB)        // 18432
#define SM_AF 0
#define SM_BF (1 * MAT_BYTES)
#define STG_BYTES (2 * MAT_BYTES)     // 36864
#define GEMM_SMEM (3 * STG_BYTES)     // 110592 (2 CTAs = 216KB <= 228KB/SM)

#define GEMM_MAINLOOP(Af, Bf, K)                                              \
    extern __shared__ char dsm[];                                             \
    const uint32_t sbase = smem_u32(dsm);                                     \
    const int tid  = threadIdx.x;                                             \
    const int lane = tid & 31;                                                \
    const int wid  = tid >> 5;                                                \
    const int wm   = wid & 3;                                                 \
    const int wn   = wid >> 2;                                                \
    const int bm   = blockIdx.y * GBM;                                        \
    const int bn   = blockIdx.x * GBN;                                        \
    const int NK   = (K) / GBK;                                               \
    float acc[2][8][4];                                                       \
    _Pragma("unroll")                                                         \
    for (int i = 0; i < 2; i++)                                               \
        _Pragma("unroll")                                                     \
        for (int j = 0; j < 8; j++)                                           \
            _Pragma("unroll")                                                 \
            for (int c = 0; c < 4; c++) acc[i][j][c] = 0.f;                   \
    auto load_stage = [&](int k0, int s) {                                    \
        const uint32_t sb = sbase + s * STG_BYTES;                            \
        _Pragma("unroll")                                                     \
        for (int i = 0; i < 4; i++) {                                         \
            const int c   = tid + i * 256;   /* 1024 chunks per matrix */     \
            const int row = c >> 3, j = c & 7;                                \
            const uint32_t off = (uint32_t)(row * ROWB + j * 16);             \
            const size_t ga = (size_t)(bm + row) * (K) + k0 + j * 8;          \
            const size_t gb = (size_t)(bn + row) * (K) + k0 + j * 8;          \
            cpa16(sb + SM_AF + off, (Af) + ga);                               \
            cpa16(sb + SM_BF + off, (Bf) + gb);                               \
        }                                                                     \
        cpa_commit();                                                         \
    };                                                                        \
    load_stage(0, 0);                                                         \
    load_stage(GBK, 1);                                                       \
    const int a_row = (lane & 15);                                            \
    const int a_kof = (lane >> 4) << 3;                                       \
    const int b_nof = (lane & 7) + ((lane >> 4) << 3);                        \
    const int b_kof = ((lane >> 3) & 1) << 3;                                 \
    for (int k = 0; k < NK; k++) {                                            \
        if (k + 1 < NK) cpa_wait<1>(); else cpa_wait<0>();                    \
        __syncthreads();                                                      \
        if (k + 2 < NK) load_stage((k + 2) * GBK, (k + 2) % 3);               \
        const uint32_t sb = sbase + (k % 3) * STG_BYTES;                      \
        _Pragma("unroll")                                                     \
        for (int kk = 0; kk < GBK; kk += 16) {                                \
            uint32_t af[2][4];                                                \
            _Pragma("unroll")                                                 \
            for (int mf = 0; mf < 2; mf++) {                                  \
                const uint32_t ad = sb + SM_AF +                              \
                    (wm * 32 + mf * 16 + a_row) * ROWB + (kk + a_kof) * 2;    \
                ldm_x4(af[mf], ad);                                           \
            }                                                                 \
            _Pragma("unroll")                                                 \
            for (int j = 0; j < 4; j++) {                                     \
                uint32_t bf[4];                                               \
                const uint32_t bd = sb + SM_BF +                              \
                    (wn * 64 + j * 16 + b_nof) * ROWB + (kk + b_kof) * 2;     \
                ldm_x4(bf, bd);                                               \
                _Pragma("unroll")                                             \
                for (int mf = 0; mf < 2; mf++) {                              \
                    mma16816h(acc[mf][2 * j + 0], af[mf], &bf[0]);            \
                    mma16816h(acc[mf][2 * j + 1], af[mf], &bf[2]);            \
                }                                                             \
            }                                                                 \
        }                                                                     \
    }

// ---------------------------------------------------------------------------
// QKV GEMM with fused bias + RoPE (table) + fp16 store into g_qf/g_kf/g_vf.
// ---------------------------------------------------------------------------
__global__ __launch_bounds__(256, 2)
void gemm_qkv(const __half* __restrict__ Af,
              const __half* __restrict__ Bf)
{
    GEMM_MAINLOOP(Af, Bf, HID)

    const int which = bn / HID;              // 0=q, 1=k, 2=v (CTA-uniform)
    __half* dst = (which == 0) ? g_qf : (which == 1) ? g_kf : g_vf;

#pragma unroll
    for (int mf = 0; mf < 2; mf++) {
        const int r0 = bm + wm * 32 + mf * 16 + (lane >> 2);
#pragma unroll
        for (int nf = 0; nf < 8; nf++) {
            const int c0 = bn + wn * 64 + nf * 8 + (lane & 3) * 2;  // even
            const float b0 = g_bq[c0], b1 = g_bq[c0 + 1];
            const int local = c0 - which * HID;
            float x00 = acc[mf][nf][0] + b0, x01 = acc[mf][nf][1] + b1;
            float x10 = acc[mf][nf][2] + b0, x11 = acc[mf][nf][3] + b1;
            if (which == 2) {
                *(__half2*)(dst + (size_t)r0 * HID + local) =
                    __floats2half2_rn(x00, x01);
                *(__half2*)(dst + (size_t)(r0 + 8) * HID + local) =
                    __floats2half2_rn(x10, x11);
            } else {
                const int i = (local % 80) >> 1;     // rope pair index
                const float4 ra = g_rope[(size_t)r0 * 40 + i];
                const float4 rb = g_rope[(size_t)(r0 + 8) * 40 + i];
                float o00 = x00 * ra.x - x01 * ra.z;
                float o01 = x01 * ra.y + x00 * ra.w;
                float o10 = x10 * rb.x - x11 * rb.z;
                float o11 = x11 * rb.y + x10 * rb.w;
                if (which == 0) {
                    o00 *= QSCALE; o01 *= QSCALE;
                    o10 *= QSCALE; o11 *= QSCALE;
                }
                *(__half2*)(dst + (size_t)r0 * HID + local) =
                    __floats2half2_rn(o00, o01);
                *(__half2*)(dst + (size_t)(r0 + 8) * HID + local) =
                    __floats2half2_rn(o10, o11);
            }
        }
    }
}

// ---------------------------------------------------------------------------
// Proj GEMM: fp32 output + bias (final result)
// ---------------------------------------------------------------------------
__global__ __launch_bounds__(256, 2)
void gemm_proj(const __half* __restrict__ Af,
               const __half* __restrict__ Bf,
               const float* __restrict__ bias, float* __restrict__ C)
{
    GEMM_MAINLOOP(Af, Bf, HID)

    const int N = HID;
#pragma unroll
    for (int mf = 0; mf < 2; mf++) {
        const int r0 = bm + wm * 32 + mf * 16 + (lane >> 2);
#pragma unroll
        for (int nf = 0; nf < 8; nf++) {
            const int c0 = bn + wn * 64 + nf * 8 + (lane & 3) * 2;
            const float b0 = bias[c0], b1 = bias[c0 + 1];
            float2 v0 = {acc[mf][nf][0] + b0, acc[mf][nf][1] + b1};
            float2 v1 = {acc[mf][nf][2] + b0, acc[mf][nf][3] + b1};
            *(float2*)(C + (size_t)r0 * N + c0) = v0;
            *(float2*)(C + (size_t)(r0 + 8) * N + c0) = v1;
        }
    }
}

// ---------------------------------------------------------------------------
// HMMA flash attention, plain fp16 operands (fp32 accumulate).
// CTA = (chunk, head, 128 q rows); 8 warps x 16 rows.
// 3-stage cp.async KV pipeline, single sync per iter, 2 CTAs/SM.
// ---------------------------------------------------------------------------
#define ARB 176
#define AQ_BYTES (128 * ARB)
#define AKV_BYTES (64 * ARB)
#define A_STG (2 * AKV_BYTES)
#define ATTN_SMEM (AQ_BYTES + 3 * A_STG)   // 90112
#define AK_OFF 0
#define AV_OFF AKV_BYTES

__global__ __launch_bounds__(256, 2)
void attn_mma()
{
    extern __shared__ char dsm[];
    const uint32_t sbase = smem_u32(dsm);
    const uint32_t SQ = sbase;
    const uint32_t SKV0 = sbase + AQ_BYTES;

    const int tid  = threadIdx.x;
    const int lane = tid & 31;
    const int wid  = tid >> 5;
    const int nc = blockIdx.y >> 4;
    const int h  = blockIdx.y & 15;
    const int t0 = nc * CH + blockIdx.x * 128;

    const int a_row = (lane & 15);
    const int a_kof = (lane >> 4) << 3;
    const int b_nof = (lane & 7) + ((lane >> 4) << 3);
    const int b_kof = ((lane >> 3) & 1) << 3;
    const int v_row = (lane & 15);
    const int v_cof = (lane >> 4) << 3;

    for (int i = tid; i < 1280; i += 256) {
        const int r = i / 10, c = i % 10;
        const uint32_t off = (uint32_t)(r * ARB + c * 16);
        const size_t src = (size_t)(t0 + r) * HID + h * HD + c * 8;
        cpa16(SQ + off, g_qf + src);
    }
    auto load_kv = [&](int kb, int s) {
        const uint32_t sb = SKV0 + s * A_STG;
        for (int i = tid; i < 640; i += 256) {
            const int r = i / 10, c = i % 10;
            const uint32_t off = (uint32_t)(r * ARB + c * 16);
            const size_t src = (size_t)(nc * CH + kb * 64 + r) * HID + h * HD + c * 8;
            cpa16(sb + AK_OFF + off, g_kf + src);
            cpa16(sb + AV_OFF + off, g_vf + src);
        }
        cpa_commit();
    };
    load_kv(0, 0);
    load_kv(1, 1);

    float o[10][4];
#pragma unroll
    for (int n = 0; n < 10; n++)
#pragma unroll
        for (int c = 0; c < 4; c++) o[n][c] = 0.f;
    float m0 = -1e30f, m1 = -1e30f, l0 = 0.f, l1 = 0.f;

    for (int kb = 0; kb < 16; kb++) {
        if (kb < 14) cpa_wait<1>(); else cpa_wait<0>();
        __syncthreads();
        if (kb + 2 < 16) load_kv(kb + 2, (kb + 2) % 3);

        const uint32_t sb = SKV0 + (kb % 3) * A_STG;

        float s[8][4];
#pragma unroll
        for (int j = 0; j < 8; j++)
#pragma unroll
            for (int c = 0; c < 4; c++) s[j][c] = 0.f;

#pragma unroll
        for (int kt = 0; kt < 5; kt++) {
            uint32_t af[4];
            const uint32_t ad = SQ + (wid * 16 + a_row) * ARB +
                                (kt * 16 + a_kof) * 2;
            ldm_x4(af, ad);
#pragma unroll
            for (int g = 0; g < 4; g++) {
                uint32_t bf[4];
                const uint32_t bd = sb + AK_OFF + (g * 16 + b_nof) * ARB +
                                    (kt * 16 + b_kof) * 2;
                ldm_x4(bf, bd);
                mma16816h(s[2 * g + 0], af, &bf[0]);
                mma16816h(s[2 * g + 1], af, &bf[2]);
            }
        }

        float mb0 = -1e30f, mb1 = -1e30f;
#pragma unroll
        for (int j = 0; j < 8; j++) {
            mb0 = fmaxf(mb0, fmaxf(s[j][0], s[j][1]));
            mb1 = fmaxf(mb1, fmaxf(s[j][2], s[j][3]));
        }
        mb0 = fmaxf(mb0, __shfl_xor_sync(0xffffffffu, mb0, 1));
        mb0 = fmaxf(mb0, __shfl_xor_sync(0xffffffffu, mb0, 2));
        mb1 = fmaxf(mb1, __shfl_xor_sync(0xffffffffu, mb1, 1));
        mb1 = fmaxf(mb1, __shfl_xor_sync(0xffffffffu, mb1, 2));

        const float mn0 = fmaxf(m0, mb0), mn1 = fmaxf(m1, mb1);
        const float alpha0 = exp2f(m0 - mn0);
        const float alpha1 = exp2f(m1 - mn1);
        m0 = mn0; m1 = mn1;

        float sum0 = 0.f, sum1 = 0.f;
#pragma unroll
        for (int j = 0; j < 8; j++) {
            s[j][0] = exp2f(s[j][0] - m0); sum0 += s[j][0];
            s[j][1] = exp2f(s[j][1] - m0); sum0 += s[j][1];
            s[j][2] = exp2f(s[j][2] - m1); sum1 += s[j][2];
            s[j][3] = exp2f(s[j][3] - m1); sum1 += s[j][3];
        }
        sum0 += __shfl_xor_sync(0xffffffffu, sum0, 1);
        sum0 += __shfl_xor_sync(0xffffffffu, sum0, 2);
        sum1 += __shfl_xor_sync(0xffffffffu, sum1, 1);
        sum1 += __shfl_xor_sync(0xffffffffu, sum1, 2);
        l0 = l0 * alpha0 + sum0;
        l1 = l1 * alpha1 + sum1;

#pragma unroll
        for (int n = 0; n < 10; n++) {
            o[n][0] *= alpha0; o[n][1] *= alpha0;
            o[n][2] *= alpha1; o[n][3] *= alpha1;
        }

#pragma unroll
        for (int t = 0; t < 4; t++) {
            uint32_t ph[4];
            const float* f0 = s[2 * t];
            const float* f1 = s[2 * t + 1];
            ph[0] = pack_f16(f0[0], f0[1]);
            ph[1] = pack_f16(f0[2], f0[3]);
            ph[2] = pack_f16(f1[0], f1[1]);
            ph[3] = pack_f16(f1[2], f1[3]);
#pragma unroll
            for (int v = 0; v < 5; v++) {
                uint32_t vf[4];
                const uint32_t vd = sb + AV_OFF + (t * 16 + v_row) * ARB +
                                    (v * 16 + v_cof) * 2;
                ldm_x4_t(vf, vd);
                mma16816h(o[2 * v + 0], ph, &vf[0]);
                mma16816h(o[2 * v + 1], ph, &vf[2]);
            }
        }
    }

    const float li0 = 1.f / l0, li1 = 1.f / l1;
    const int r0 = t0 + wid * 16 + (lane >> 2);
    const size_t colb = h * HD + 2 * (lane & 3);
#pragma unroll
    for (int n = 0; n < 10; n++) {
        const size_t p0 = (size_t)r0 * HID + colb + n * 8;
        const size_t p1 = (size_t)(r0 + 8) * HID + colb + n * 8;
        *(__half2*)(g_af + p0) = __floats2half2_rn(o[n][0] * li0, o[n][1] * li0);
        *(__half2*)(g_af + p1) = __floats2half2_rn(o[n][2] * li1, o[n][3] * li1);
    }
}

// ---------------------------------------------------------------------------
extern "C" void kernel_launch(void* const* d_in, const int* in_sizes, int n_in,
                              void* d_out, int out_size)
{
    const float* x      = (const float*)d_in[0];
    const float* cosb   = (const float*)d_in[2];
    const float* sinb   = (const float*)d_in[3];
    const float* w_qkv  = (const float*)d_in[4];
    const float* b_qkv  = (const float*)d_in[5];
    const float* w_proj = (const float*)d_in[6];
    const float* b_proj = (const float*)d_in[7];
    float* out = (float*)d_out;

    __half *xf, *wq, *wp, *af;
    cudaGetSymbolAddress((void**)&xf, g_xf);
    cudaGetSymbolAddress((void**)&wq, g_wq);
    cudaGetSymbolAddress((void**)&wp, g_wp);
    cudaGetSymbolAddress((void**)&af, g_af);

    cudaFuncSetAttribute(gemm_qkv,
                         cudaFuncAttributeMaxDynamicSharedMemorySize, GEMM_SMEM);
    cudaFuncSetAttribute(gemm_proj,
                         cudaFuncAttributeMaxDynamicSharedMemorySize, GEMM_SMEM);
    cudaFuncSetAttribute(attn_mma,
                         cudaFuncAttributeMaxDynamicSharedMemorySize, ATTN_SMEM);

    prep_all<<<(SEG3 + 255) / 256, 256>>>(x, w_qkv, b_qkv, w_proj, cosb, sinb);

    gemm_qkv<<<dim3(3 * HID / GBN, S_LEN / GBM), 256, GEMM_SMEM>>>(xf, wq);

    attn_mma<<<dim3(8, NC * NH), 256, ATTN_SMEM>>>();

    gemm_proj<<<dim3(HID / GBN, S_LEN / GBM), 256, GEMM_SMEM>>>(
        af, wp, b_proj, out);
}

// round 16
// speedup vs baseline: 1.0546x; 1.0546x over previous
#include <cuda_runtime.h>
#include <cuda_bf16.h>
#include <cuda_fp16.h>
#include <cstdint>
#include <math.h>

#define S_LEN 16384
#define HID 1280
#define NH 16
#define HD 80
#define NC 16
#define CH 1024

// ---------------------------------------------------------------------------
// Scratch (no cudaMalloc allowed)
// ---------------------------------------------------------------------------
__device__ __align__(256) __half g_xf[(size_t)S_LEN * HID];
__device__ __align__(256) __half g_wq[(size_t)3 * HID * HID];  // q/k rows PERMUTED
__device__ __align__(256) float  g_bq[3 * HID];                // permuted bias
__device__ __align__(256) __half g_wp[(size_t)HID * HID];
// rope table: (cos_i, cos_{i+40}, sin_i, sin_{i+40}) per (t, pair i)
__device__ __align__(256) float4 g_rope[(size_t)S_LEN * 40];
// attention inputs: plain fp16, q/k in rope-permuted d-layout,
// q pre-scaled by 1/sqrt(80)*log2e
__device__ __align__(256) __half g_qf[(size_t)S_LEN * HID];
__device__ __align__(256) __half g_kf[(size_t)S_LEN * HID];
__device__ __align__(256) __half g_vf[(size_t)S_LEN * HID];
// attention output = proj GEMM activation (fp16)
__device__ __align__(256) __half g_af[(size_t)S_LEN * HID];

#define QSCALE 0.16130856f   // 0.11180339887 * 1.44269504089

// ---------------------------------------------------------------------------
// helpers (sm_80-era instructions only — harness compiles for plain sm_103)
// ---------------------------------------------------------------------------
__device__ __forceinline__ uint32_t smem_u32(const void* p) {
    uint32_t a;
    asm("{ .reg .u64 t; cvta.to.shared.u64 t, %1; cvt.u32.u64 %0, t; }"
        : "=r"(a) : "l"(p));
    return a;
}

// L1-allocating cp.async: co-resident CTAs share B / KV tiles -> L1 hits
__device__ __forceinline__ void cpa16(uint32_t dst, const void* src) {
    asm volatile("cp.async.ca.shared.global [%0], [%1], 16;\n"
                 :: "r"(dst), "l"(src));
}
__device__ __forceinline__ void cpa_commit() {
    asm volatile("cp.async.commit_group;\n" ::: "memory");
}
template <int N>
__device__ __forceinline__ void cpa_wait() {
    asm volatile("cp.async.wait_group %0;\n" :: "n"(N) : "memory");
}

__device__ __forceinline__ void ldm_x4(uint32_t* r, uint32_t addr) {
    asm volatile("ldmatrix.sync.aligned.m8n8.x4.shared.b16 {%0,%1,%2,%3}, [%4];"
                 : "=r"(r[0]), "=r"(r[1]), "=r"(r[2]), "=r"(r[3])
                 : "r"(addr));
}
__device__ __forceinline__ void ldm_x4_t(uint32_t* r, uint32_t addr) {
    asm volatile(
        "ldmatrix.sync.aligned.m8n8.x4.trans.shared.b16 {%0,%1,%2,%3}, [%4];"
        : "=r"(r[0]), "=r"(r[1]), "=r"(r[2]), "=r"(r[3])
        : "r"(addr));
}

__device__ __forceinline__ void mma16816h(float* d, const uint32_t* a,
                                          const uint32_t* b) {
    asm volatile(
        "mma.sync.aligned.m16n8k16.row.col.f32.f16.f16.f32 "
        "{%0,%1,%2,%3}, {%4,%5,%6,%7}, {%8,%9}, {%0,%1,%2,%3};"
        : "+f"(d[0]), "+f"(d[1]), "+f"(d[2]), "+f"(d[3])
        : "r"(a[0]), "r"(a[1]), "r"(a[2]), "r"(a[3]), "r"(b[0]), "r"(b[1]));
}

__device__ __forceinline__ uint32_t pack_f16(float lo, float hi) {
    uint32_t d;
    asm("cvt.rn.f16x2.f32 %0, %1, %2;" : "=r"(d) : "f"(hi), "f"(lo));
    return d;
}

// ---------------------------------------------------------------------------
// Fused prep: x cvt | wq perm cvt (+bias) | wp cvt | rope table
// ---------------------------------------------------------------------------
#define N_X   (S_LEN * HID)
#define N_WQ  (3 * HID * HID)
#define N_WP  (HID * HID)
#define SEG0  (N_X / 4)
#define SEG1  (SEG0 + N_WQ / 4)
#define SEG2  (SEG1 + N_WP / 4)
#define SEG3  (SEG2 + S_LEN * 40)

__global__ void prep_all(const float* __restrict__ x,
                         const float* __restrict__ w_qkv,
                         const float* __restrict__ b_qkv,
                         const float* __restrict__ w_proj,
                         const float* __restrict__ cosb,
                         const float* __restrict__ sinb)
{
    int u = blockIdx.x * blockDim.x + threadIdx.x;
    if (u < SEG0) {
        const int i = u * 4;
        float4 v = *(const float4*)(x + i);
        *(__half2*)(g_xf + i)     = __floats2half2_rn(v.x, v.y);
        *(__half2*)(g_xf + i + 2) = __floats2half2_rn(v.z, v.w);
    } else if (u < SEG1) {
        const int i = (u - SEG0) * 4;
        const int p  = i / HID;
        const int kk = i % HID;
        const int which = p / HID;
        int n = p;
        if (which < 2) {
            const int pl = p % HID;
            const int h = pl / 80, j = pl % 80;
            const int d = (j & 1) ? (j >> 1) + 40 : (j >> 1);
            n = which * HID + h * 80 + d;
        }
        float4 v = *(const float4*)(w_qkv + (size_t)n * HID + kk);
        *(__half2*)(g_wq + (size_t)p * HID + kk)     = __floats2half2_rn(v.x, v.y);
        *(__half2*)(g_wq + (size_t)p * HID + kk + 2) = __floats2half2_rn(v.z, v.w);
        if (kk == 0) g_bq[p] = b_qkv[n];
    } else if (u < SEG2) {
        const int i = (u - SEG1) * 4;
        float4 v = *(const float4*)(w_proj + i);
        *(__half2*)(g_wp + i)     = __floats2half2_rn(v.x, v.y);
        *(__half2*)(g_wp + i + 2) = __floats2half2_rn(v.z, v.w);
    } else if (u < SEG3) {
        const int e = u - SEG2;
        const int t = e / 40, i = e % 40;
        float4 r;
        r.x = cosb[t * HD + i];
        r.y = cosb[t * HD + i + 40];
        r.z = sinb[t * HD + i];
        r.w = sinb[t * HD + i + 40];
        g_rope[e] = r;
    }
}

// ---------------------------------------------------------------------------
// fp16 GEMM mainloop: block 128x128, K-chunk 64, 8 warps (4M x 2N),
// warp tile 32x64. 2-stage cp.async, single __syncthreads per K-iter
// (prefetch issued post-barrier, overlaps compute). 2 CTAs/SM.
// Row stride 144B -> conflict-free ldmatrix (9*row mod 8 distinct).
// ---------------------------------------------------------------------------
#define GBM 128
#define GBN 128
#define GBK 64
#define ROWB 144
#define MAT_BYTES (128 * ROWB)        // 18432
#define SM_AF 0
#define SM_BF (1 * MAT_BYTES)
#define STG_BYTES (2 * MAT_BYTES)     // 36864
#define GEMM_SMEM (2 * STG_BYTES)     // 73728

#define GEMM_MAINLOOP(Af, Bf, K)                                              \
    extern __shared__ char dsm[];                                             \
    const uint32_t sbase = smem_u32(dsm);                                     \
    const int tid  = threadIdx.x;                                             \
    const int lane = tid & 31;                                                \
    const int wid  = tid >> 5;                                                \
    const int wm   = wid & 3;                                                 \
    const int wn   = wid >> 2;                                                \
    const int bm   = blockIdx.y * GBM;                                        \
    const int bn   = blockIdx.x * GBN;                                        \
    const int NK   = (K) / GBK;                                               \
    float acc[2][8][4];                                                       \
    _Pragma("unroll")                                                         \
    for (int i = 0; i < 2; i++)                                               \
        _Pragma("unroll")                                                     \
        for (int j = 0; j < 8; j++)                                           \
            _Pragma("unroll")                                                 \
            for (int c = 0; c < 4; c++) acc[i][j][c] = 0.f;                   \
    auto load_stage = [&](int k0, int s) {                                    \
        const uint32_t sb = sbase + s * STG_BYTES;                            \
        _Pragma("unroll")                                                     \
        for (int i = 0; i < 4; i++) {                                         \
            const int c   = tid + i * 256;   /* 1024 chunks per matrix */     \
            const int row = c >> 3, j = c & 7;                                \
            const uint32_t off = (uint32_t)(row * ROWB + j * 16);             \
            const size_t ga = (size_t)(bm + row) * (K) + k0 + j * 8;          \
            const size_t gb = (size_t)(bn + row) * (K) + k0 + j * 8;          \
            cpa16(sb + SM_AF + off, (Af) + ga);                               \
            cpa16(sb + SM_BF + off, (Bf) + gb);                               \
        }                                                                     \
        cpa_commit();                                                         \
    };                                                                        \
    load_stage(0, 0);                                                         \
    const int a_row = (lane & 15);                                            \
    const int a_kof = (lane >> 4) << 3;                                       \
    const int b_nof = (lane & 7) + ((lane >> 4) << 3);                        \
    const int b_kof = ((lane >> 3) & 1) << 3;                                 \
    for (int k = 0; k < NK; k++) {                                            \
        cpa_wait<0>();                                                        \
        __syncthreads();                                                      \
        if (k + 1 < NK) load_stage((k + 1) * GBK, (k + 1) & 1);               \
        const uint32_t sb = sbase + (k & 1) * STG_BYTES;                      \
        _Pragma("unroll")                                                     \
        for (int kk = 0; kk < GBK; kk += 16) {                                \
            uint32_t af[2][4];                                                \
            _Pragma("unroll")                                                 \
            for (int mf = 0; mf < 2; mf++) {                                  \
                const uint32_t ad = sb + SM_AF +                              \
                    (wm * 32 + mf * 16 + a_row) * ROWB + (kk + a_kof) * 2;    \
                ldm_x4(af[mf], ad);                                           \
            }                                                                 \
            _Pragma("unroll")                                                 \
            for (int j = 0; j < 4; j++) {                                     \
                uint32_t bf[4];                                               \
                const uint32_t bd = sb + SM_BF +                              \
                    (wn * 64 + j * 16 + b_nof) * ROWB + (kk + b_kof) * 2;     \
                ldm_x4(bf, bd);                                               \
                _Pragma("unroll")                                             \
                for (int mf = 0; mf < 2; mf++) {                              \
                    mma16816h(acc[mf][2 * j + 0], af[mf], &bf[0]);            \
                    mma16816h(acc[mf][2 * j + 1], af[mf], &bf[2]);            \
                }                                                             \
            }                                                                 \
        }                                                                     \
    }

// ---------------------------------------------------------------------------
// QKV GEMM with fused bias + RoPE (table) + fp16 store into g_qf/g_kf/g_vf.
// ---------------------------------------------------------------------------
__global__ __launch_bounds__(256, 2)
void gemm_qkv(const __half* __restrict__ Af,
              const __half* __restrict__ Bf)
{
    GEMM_MAINLOOP(Af, Bf, HID)

    const int which = bn / HID;              // 0=q, 1=k, 2=v (CTA-uniform)
    __half* dst = (which == 0) ? g_qf : (which == 1) ? g_kf : g_vf;

#pragma unroll
    for (int mf = 0; mf < 2; mf++) {
        const int r0 = bm + wm * 32 + mf * 16 + (lane >> 2);
#pragma unroll
        for (int nf = 0; nf < 8; nf++) {
            const int c0 = bn + wn * 64 + nf * 8 + (lane & 3) * 2;  // even
            const float b0 = g_bq[c0], b1 = g_bq[c0 + 1];
            const int local = c0 - which * HID;
            float x00 = acc[mf][nf][0] + b0, x01 = acc[mf][nf][1] + b1;
            float x10 = acc[mf][nf][2] + b0, x11 = acc[mf][nf][3] + b1;
            if (which == 2) {
                *(__half2*)(dst + (size_t)r0 * HID + local) =
                    __floats2half2_rn(x00, x01);
                *(__half2*)(dst + (size_t)(r0 + 8) * HID + local) =
                    __floats2half2_rn(x10, x11);
            } else {
                const int i = (local % 80) >> 1;     // rope pair index
                const float4 ra = g_rope[(size_t)r0 * 40 + i];
                const float4 rb = g_rope[(size_t)(r0 + 8) * 40 + i];
                float o00 = x00 * ra.x - x01 * ra.z;
                float o01 = x01 * ra.y + x00 * ra.w;
                float o10 = x10 * rb.x - x11 * rb.z;
                float o11 = x11 * rb.y + x10 * rb.w;
                if (which == 0) {
                    o00 *= QSCALE; o01 *= QSCALE;
                    o10 *= QSCALE; o11 *= QSCALE;
                }
                *(__half2*)(dst + (size_t)r0 * HID + local) =
                    __floats2half2_rn(o00, o01);
                *(__half2*)(dst + (size_t)(r0 + 8) * HID + local) =
                    __floats2half2_rn(o10, o11);
            }
        }
    }
}

// ---------------------------------------------------------------------------
// Proj GEMM: fp32 output + bias (final result)
// ---------------------------------------------------------------------------
__global__ __launch_bounds__(256, 2)
void gemm_proj(const __half* __restrict__ Af,
               const __half* __restrict__ Bf,
               const float* __restrict__ bias, float* __restrict__ C)
{
    GEMM_MAINLOOP(Af, Bf, HID)

    const int N = HID;
#pragma unroll
    for (int mf = 0; mf < 2; mf++) {
        const int r0 = bm + wm * 32 + mf * 16 + (lane >> 2);
#pragma unroll
        for (int nf = 0; nf < 8; nf++) {
            const int c0 = bn + wn * 64 + nf * 8 + (lane & 3) * 2;
            const float b0 = bias[c0], b1 = bias[c0 + 1];
            float2 v0 = {acc[mf][nf][0] + b0, acc[mf][nf][1] + b1};
            float2 v1 = {acc[mf][nf][2] + b0, acc[mf][nf][3] + b1};
            *(float2*)(C + (size_t)r0 * N + c0) = v0;
            *(float2*)(C + (size_t)(r0 + 8) * N + c0) = v1;
        }
    }
}

// ---------------------------------------------------------------------------
// HMMA flash attention, plain fp16 operands (fp32 accumulate).
// CTA = (chunk, head, 128 q rows); 8 warps x 16 rows.
// 3-stage cp.async KV pipeline, single sync per iter, 2 CTAs/SM.
// ---------------------------------------------------------------------------
#define ARB 176
#define AQ_BYTES (128 * ARB)
#define AKV_BYTES (64 * ARB)
#define A_STG (2 * AKV_BYTES)
#define ATTN_SMEM (AQ_BYTES + 3 * A_STG)   // 90112
#define AK_OFF 0
#define AV_OFF AKV_BYTES

__global__ __launch_bounds__(256, 2)
void attn_mma()
{
    extern __shared__ char dsm[];
    const uint32_t sbase = smem_u32(dsm);
    const uint32_t SQ = sbase;
    const uint32_t SKV0 = sbase + AQ_BYTES;

    const int tid  = threadIdx.x;
    const int lane = tid & 31;
    const int wid  = tid >> 5;
    const int nc = blockIdx.y >> 4;
    const int h  = blockIdx.y & 15;
    const int t0 = nc * CH + blockIdx.x * 128;

    const int a_row = (lane & 15);
    const int a_kof = (lane >> 4) << 3;
    const int b_nof = (lane & 7) + ((lane >> 4) << 3);
    const int b_kof = ((lane >> 3) & 1) << 3;
    const int v_row = (lane & 15);
    const int v_cof = (lane >> 4) << 3;

    for (int i = tid; i < 1280; i += 256) {
        const int r = i / 10, c = i % 10;
        const uint32_t off = (uint32_t)(r * ARB + c * 16);
        const size_t src = (size_t)(t0 + r) * HID + h * HD + c * 8;
        cpa16(SQ + off, g_qf + src);
    }
    auto load_kv = [&](int kb, int s) {
        const uint32_t sb = SKV0 + s * A_STG;
        for (int i = tid; i < 640; i += 256) {
            const int r = i / 10, c = i % 10;
            const uint32_t off = (uint32_t)(r * ARB + c * 16);
            const size_t src = (size_t)(nc * CH + kb * 64 + r) * HID + h * HD + c * 8;
            cpa16(sb + AK_OFF + off, g_kf + src);
            cpa16(sb + AV_OFF + off, g_vf + src);
        }
        cpa_commit();
    };
    load_kv(0, 0);
    load_kv(1, 1);

    float o[10][4];
#pragma unroll
    for (int n = 0; n < 10; n++)
#pragma unroll
        for (int c = 0; c < 4; c++) o[n][c] = 0.f;
    float m0 = -1e30f, m1 = -1e30f, l0 = 0.f, l1 = 0.f;

    for (int kb = 0; kb < 16; kb++) {
        if (kb < 14) cpa_wait<1>(); else cpa_wait<0>();
        __syncthreads();
        if (kb + 2 < 16) load_kv(kb + 2, (kb + 2) % 3);

        const uint32_t sb = SKV0 + (kb % 3) * A_STG;

        float s[8][4];
#pragma unroll
        for (int j = 0; j < 8; j++)
#pragma unroll
            for (int c = 0; c < 4; c++) s[j][c] = 0.f;

#pragma unroll
        for (int kt = 0; kt < 5; kt++) {
            uint32_t af[4];
            const uint32_t ad = SQ + (wid * 16 + a_row) * ARB +
                                (kt * 16 + a_kof) * 2;
            ldm_x4(af, ad);
#pragma unroll
            for (int g = 0; g < 4; g++) {
                uint32_t bf[4];
                const uint32_t bd = sb + AK_OFF + (g * 16 + b_nof) * ARB +
                                    (kt * 16 + b_kof) * 2;
                ldm_x4(bf, bd);
                mma16816h(s[2 * g + 0], af, &bf[0]);
                mma16816h(s[2 * g + 1], af, &bf[2]);
            }
        }

        float mb0 = -1e30f, mb1 = -1e30f;
#pragma unroll
        for (int j = 0; j < 8; j++) {
            mb0 = fmaxf(mb0, fmaxf(s[j][0], s[j][1]));
            mb1 = fmaxf(mb1, fmaxf(s[j][2], s[j][3]));
        }
        mb0 = fmaxf(mb0, __shfl_xor_sync(0xffffffffu, mb0, 1));
        mb0 = fmaxf(mb0, __shfl_xor_sync(0xffffffffu, mb0, 2));
        mb1 = fmaxf(mb1, __shfl_xor_sync(0xffffffffu, mb1, 1));
        mb1 = fmaxf(mb1, __shfl_xor_sync(0xffffffffu, mb1, 2));

        const float mn0 = fmaxf(m0, mb0), mn1 = fmaxf(m1, mb1);
        const float alpha0 = exp2f(m0 - mn0);
        const float alpha1 = exp2f(m1 - mn1);
        m0 = mn0; m1 = mn1;

        float sum0 = 0.f, sum1 = 0.f;
#pragma unroll
        for (int j = 0; j < 8; j++) {
            s[j][0] = exp2f(s[j][0] - m0); sum0 += s[j][0];
            s[j][1] = exp2f(s[j][1] - m0); sum0 += s[j][1];
            s[j][2] = exp2f(s[j][2] - m1); sum1 += s[j][2];
            s[j][3] = exp2f(s[j][3] - m1); sum1 += s[j][3];
        }
        sum0 += __shfl_xor_sync(0xffffffffu, sum0, 1);
        sum0 += __shfl_xor_sync(0xffffffffu, sum0, 2);
        sum1 += __shfl_xor_sync(0xffffffffu, sum1, 1);
        sum1 += __shfl_xor_sync(0xffffffffu, sum1, 2);
        l0 = l0 * alpha0 + sum0;
        l1 = l1 * alpha1 + sum1;

#pragma unroll
        for (int n = 0; n < 10; n++) {
            o[n][0] *= alpha0; o[n][1] *= alpha0;
            o[n][2] *= alpha1; o[n][3] *= alpha1;
        }

#pragma unroll
        for (int t = 0; t < 4; t++) {
            uint32_t ph[4];
            const float* f0 = s[2 * t];
            const float* f1 = s[2 * t + 1];
            ph[0] = pack_f16(f0[0], f0[1]);
            ph[1] = pack_f16(f0[2], f0[3]);
            ph[2] = pack_f16(f1[0], f1[1]);
            ph[3] = pack_f16(f1[2], f1[3]);
#pragma unroll
            for (int v = 0; v < 5; v++) {
                uint32_t vf[4];
                const uint32_t vd = sb + AV_OFF + (t * 16 + v_row) * ARB +
                                    (v * 16 + v_cof) * 2;
                ldm_x4_t(vf, vd);
                mma16816h(o[2 * v + 0], ph, &vf[0]);
                mma16816h(o[2 * v + 1], ph, &vf[2]);
            }
        }
    }

    const float li0 = 1.f / l0, li1 = 1.f / l1;
    const int r0 = t0 + wid * 16 + (lane >> 2);
    const size_t colb = h * HD + 2 * (lane & 3);
#pragma unroll
    for (int n = 0; n < 10; n++) {
        const size_t p0 = (size_t)r0 * HID + colb + n * 8;
        const size_t p1 = (size_t)(r0 + 8) * HID + colb + n * 8;
        *(__half2*)(g_af + p0) = __floats2half2_rn(o[n][0] * li0, o[n][1] * li0);
        *(__half2*)(g_af + p1) = __floats2half2_rn(o[n][2] * li1, o[n][3] * li1);
    }
}

// ---------------------------------------------------------------------------
extern "C" void kernel_launch(void* const* d_in, const int* in_sizes, int n_in,
                              void* d_out, int out_size)
{
    const float* x      = (const float*)d_in[0];
    const float* cosb   = (const float*)d_in[2];
    const float* sinb   = (const float*)d_in[3];
    const float* w_qkv  = (const float*)d_in[4];
    const float* b_qkv  = (const float*)d_in[5];
    const float* w_proj = (const float*)d_in[6];
    const float* b_proj = (const float*)d_in[7];
    float* out = (float*)d_out;

    __half *xf, *wq, *wp, *af;
    cudaGetSymbolAddress((void**)&xf, g_xf);
    cudaGetSymbolAddress((void**)&wq, g_wq);
    cudaGetSymbolAddress((void**)&wp, g_wp);
    cudaGetSymbolAddress((void**)&af, g_af);

    cudaFuncSetAttribute(gemm_qkv,
                         cudaFuncAttributeMaxDynamicSharedMemorySize, GEMM_SMEM);
    cudaFuncSetAttribute(gemm_proj,
                         cudaFuncAttributeMaxDynamicSharedMemorySize, GEMM_SMEM);
    cudaFuncSetAttribute(attn_mma,
                         cudaFuncAttributeMaxDynamicSharedMemorySize, ATTN_SMEM);

    prep_all<<<(SEG3 + 255) / 256, 256>>>(x, w_qkv, b_qkv, w_proj, cosb, sinb);

    gemm_qkv<<<dim3(3 * HID / GBN, S_LEN / GBM), 256, GEMM_SMEM>>>(xf, wq);

    attn_mma<<<dim3(8, NC * NH), 256, ATTN_SMEM>>>();

    gemm_proj<<<dim3(HID / GBN, S_LEN / GBM), 256, GEMM_SMEM>>>(
        af, wp, b_proj, out);
}